// round 9
// baseline (speedup 1.0000x reference)
#include <cuda_runtime.h>
#include <cuda_bf16.h>
#include <cstdint>
#include <cstddef>

namespace {
constexpr int Bn   = 1024;
constexpr int BnP  = 1032;   // padded rows (zero tail)
constexpr int Tn   = 512;
constexpr int Hn   = 64;
constexpr int NB   = 7;      // real rows per block -> grid 147 (N=8 with pad row)
constexpr int GRID = 147;
constexpr int NT   = 512;    // 16 warps
}

// Inter-layer activations, [t][b][64], f32, rows >=1024 stay zero.
__device__ float g_seq0[(size_t)Tn * BnP * 64];
__device__ float g_seq1[(size_t)Tn * BnP * 64];
// Layer-0 input transposed+padded: [t][b][64] (cols 22..63 zero)
__device__ float g_x64[(size_t)Tn * BnP * 64];

__device__ __forceinline__ float htanh(float x) {   // HW MUFU.TANH
    float y;
    asm("tanh.approx.f32 %0, %1;" : "=f"(y) : "f"(x));
    return y;
}
__device__ __forceinline__ float sigm(float x) {    // 0.5 + 0.5*tanh(x/2)
    return fmaf(htanh(0.5f * x), 0.5f, 0.5f);
}
__device__ __forceinline__ uint32_t bf2(float a, float b) {
    __nv_bfloat162 t = __floats2bfloat162_rn(a, b);
    return *reinterpret_cast<uint32_t*>(&t);
}
__device__ __forceinline__ float bfr(float v) {
    return __bfloat162float(__float2bfloat16(v));
}

// m16n8k16 bf16 MMA, fp32 accumulate (sm_80 baseline PTX).
__device__ __forceinline__ void hmma(float& d0, float& d1, float& d2, float& d3,
                                     uint32_t a0, uint32_t a1, uint32_t a2, uint32_t a3,
                                     uint32_t b0, uint32_t b1) {
    asm volatile(
        "mma.sync.aligned.m16n8k16.row.col.f32.bf16.bf16.f32 "
        "{%0,%1,%2,%3}, {%4,%5,%6,%7}, {%8,%9}, {%0,%1,%2,%3};"
        : "+f"(d0), "+f"(d1), "+f"(d2), "+f"(d3)
        : "r"(a0), "r"(a1), "r"(a2), "r"(a3), "r"(b0), "r"(b1));
}

// Transpose x[b][22][t] -> g_x64[t][b][0..63] (cols 22..63 zero).
__global__ void __launch_bounds__(256)
transpose_x_k(const float* __restrict__ x)
{
    const int b  = blockIdx.x >> 3;
    const int t0 = (blockIdx.x & 7) * 64;
    __shared__ float tile[22][65];
    for (int e = threadIdx.x; e < 22 * 64; e += 256) {
        int i = e / 64, tt = e - i * 64;
        tile[i][tt] = x[(size_t)b * (22 * Tn) + i * Tn + t0 + tt];
    }
    __syncthreads();
    for (int e = threadIdx.x; e < 64 * 64; e += 256) {
        int tt = e >> 6, i = e & 63;
        g_x64[((size_t)(t0 + tt) * BnP + b) * 64 + i] = (i < 22) ? tile[i][tt] : 0.f;
    }
}

// LSTM layer on HMMA tensor cores.
// B tile bf16 hi/lo, row stride 200 (u32 stride 100 -> conflict-free frags):
//   cols [0,64)    x slot 0   (parity double-buffer)
//   cols [64,128)  x slot 1
//   cols [128,192) h_{t-1}
// Per step:  bar1 -> hMMA (W_h·h, init = carried xproj(t)) -> exchange ->
// bar2 -> { combine (MUFU) || xproj(t+1) (tensor) } -> loop.
template<int LAYER>
__global__ void __launch_bounds__(NT, 1)
lstm_hmma_k(const float* __restrict__ w_ih, const float* __restrict__ w_hh,
            const float* __restrict__ b_ih, const float* __restrict__ b_hh,
            const float* __restrict__ w_fc, const float* __restrict__ b_fc,
            float* __restrict__ out_fc)
{
    constexpr bool LAST = (LAYER == 2);
    constexpr int  DIN  = (LAYER == 0) ? 22 : 64;
    constexpr int  XCH  = (LAYER == 0) ? 2 : 4;     // x k-chunks (cols >=32 zero for L0)
    const float* xin  = (LAYER == 0) ? g_x64 : (LAYER == 1 ? g_seq0 : g_seq1);
    float*       outs = (LAYER == 0) ? g_seq0 : (LAYER == 1 ? g_seq1 : nullptr);

    __shared__ __align__(16) __nv_bfloat16 in_hi[8][200];
    __shared__ __align__(16) __nv_bfloat16 in_lo[8][200];
    __shared__ float gates_s[8][268];
    __shared__ float h_s[8][64];

    const int tid  = threadIdx.x;
    const int lane = tid & 31;
    const int wrp  = tid >> 5;
    const int gid  = lane >> 2;
    const int qid  = lane & 3;
    const int G    = wrp * 16;
    const int b0   = blockIdx.x * NB;
    const int nrows = (Bn - b0 < NB) ? (Bn - b0) : NB;

    // ---- weight fragments (hi + lo bf16 split), registers ----
    const int m0 = G + gid;
    const int m1 = G + 8 + gid;
    uint32_t axh[XCH][4], axl[XCH][4];   // x cols [0,64)
    uint32_t ahh[4][4],   ahl[4][4];     // h cols [64,128)
    {
        auto pair = [&](float p0, float p1, uint32_t& hi, uint32_t& lo) {
            float h0 = bfr(p0), h1 = bfr(p1);
            hi = bf2(h0, h1);
            lo = bf2(p0 - h0, p1 - h1);
        };
        auto wx = [&](int m, int k) -> float {
            return (k < DIN) ? w_ih[m * DIN + k] : 0.f;
        };
#pragma unroll
        for (int kc = 0; kc < XCH; kc++) {
            const int k0 = kc * 16 + qid * 2, k1 = k0 + 8;
            pair(wx(m0, k0), wx(m0, k0 + 1), axh[kc][0], axl[kc][0]);
            pair(wx(m1, k0), wx(m1, k0 + 1), axh[kc][1], axl[kc][1]);
            pair(wx(m0, k1), wx(m0, k1 + 1), axh[kc][2], axl[kc][2]);
            pair(wx(m1, k1), wx(m1, k1 + 1), axh[kc][3], axl[kc][3]);
        }
#pragma unroll
        for (int kc = 0; kc < 4; kc++) {
            const int k0 = kc * 16 + qid * 2, k1 = k0 + 8;
            pair(w_hh[m0 * 64 + k0], w_hh[m0 * 64 + k0 + 1], ahh[kc][0], ahl[kc][0]);
            pair(w_hh[m1 * 64 + k0], w_hh[m1 * 64 + k0 + 1], ahh[kc][1], ahl[kc][1]);
            pair(w_hh[m0 * 64 + k1], w_hh[m0 * 64 + k1 + 1], ahh[kc][2], ahl[kc][2]);
            pair(w_hh[m1 * 64 + k1], w_hh[m1 * 64 + k1 + 1], ahh[kc][3], ahl[kc][3]);
        }
    }
    const float biasA = b_ih[m0] + b_hh[m0];
    const float biasB = b_ih[m1] + b_hh[m1];

    // ---- zero B tiles ----
    for (int e = tid; e < 8 * 200; e += NT) {
        (&in_hi[0][0])[e] = __float2bfloat16(0.f);
        (&in_lo[0][0])[e] = __float2bfloat16(0.f);
    }

    // combine identity
    const int cr = tid >> 6;       // batch row (7 = pad row)
    const int cc = tid & 63;
    float cst = 0.f;

    __syncthreads();
    // stage x_0 -> slot 0, x_1 -> slot 1
    {
        float v0 = xin[((size_t)0 * BnP + b0 + cr) * 64 + cc];
        float h0 = bfr(v0);
        in_hi[cr][cc] = __float2bfloat16(h0);
        in_lo[cr][cc] = __float2bfloat16(v0 - h0);
        float v1 = (Tn > 1) ? xin[((size_t)1 * BnP + b0 + cr) * 64 + cc] : 0.f;
        float h1 = bfr(v1);
        in_hi[cr][64 + cc] = __float2bfloat16(h1);
        in_lo[cr][64 + cc] = __float2bfloat16(v1 - h1);
    }
    __syncthreads();

    const uint32_t* rowH = reinterpret_cast<const uint32_t*>(&in_hi[gid][0]) + qid;
    const uint32_t* rowL = reinterpret_cast<const uint32_t*>(&in_lo[gid][0]) + qid;

    // xproj(slot): W_x · x, bias included; result in carried cx registers.
    float cx0, cx1, cx2, cx3;
    auto xproj = [&](int slot) {
        float d0 = biasA, d1 = biasA, d2 = biasB, d3 = biasB;
        float e0 = 0.f, e1 = 0.f, e2 = 0.f, e3 = 0.f;
        float f0 = 0.f, f1 = 0.f, f2 = 0.f, f3 = 0.f;
        const int wb = 32 * slot;
#pragma unroll
        for (int kc = 0; kc < XCH; kc++) {
            const uint32_t bh0 = rowH[wb + kc * 8];
            const uint32_t bh1 = rowH[wb + kc * 8 + 4];
            const uint32_t bl0 = rowL[wb + kc * 8];
            const uint32_t bl1 = rowL[wb + kc * 8 + 4];
            hmma(d0, d1, d2, d3, axh[kc][0], axh[kc][1], axh[kc][2], axh[kc][3], bh0, bh1);
            hmma(e0, e1, e2, e3, axh[kc][0], axh[kc][1], axh[kc][2], axh[kc][3], bl0, bl1);
            hmma(f0, f1, f2, f3, axl[kc][0], axl[kc][1], axl[kc][2], axl[kc][3], bh0, bh1);
        }
        cx0 = d0 + e0 + f0; cx1 = d1 + e1 + f1;
        cx2 = d2 + e2 + f2; cx3 = d3 + e3 + f3;
    };

    xproj(0);   // carried for t=0

    for (int t = 0; t < Tn; t++) {
        __syncthreads();   // bar1: h_{t-1} staged; x slots stable; cx ready

        // ---- critical-path GEMM: W_h · h_{t-1}, init = carried xproj(t) ----
        float d0 = cx0, d1 = cx1, d2 = cx2, d3 = cx3;
        float e0 = 0.f, e1 = 0.f, e2 = 0.f, e3 = 0.f;
        float f0 = 0.f, f1 = 0.f, f2 = 0.f, f3 = 0.f;
#pragma unroll
        for (int kc = 0; kc < 4; kc++) {
            const uint32_t bh0 = rowH[64 + kc * 8];
            const uint32_t bh1 = rowH[64 + kc * 8 + 4];
            const uint32_t bl0 = rowL[64 + kc * 8];
            const uint32_t bl1 = rowL[64 + kc * 8 + 4];
            hmma(d0, d1, d2, d3, ahh[kc][0], ahh[kc][1], ahh[kc][2], ahh[kc][3], bh0, bh1);
            hmma(e0, e1, e2, e3, ahh[kc][0], ahh[kc][1], ahh[kc][2], ahh[kc][3], bl0, bl1);
            hmma(f0, f1, f2, f3, ahl[kc][0], ahl[kc][1], ahl[kc][2], ahl[kc][3], bh0, bh1);
        }
        d0 += e0 + f0; d1 += e1 + f1; d2 += e2 + f2; d3 += e3 + f3;

        // ---- exchange gates: D(m,n) -> gates_s[n][m] ----
        gates_s[qid * 2][m0]     = d0;
        gates_s[qid * 2 + 1][m0] = d1;
        gates_s[qid * 2][m1]     = d2;
        gates_s[qid * 2 + 1][m1] = d3;

        __syncthreads();   // bar2: gates ready; all B-tile reads for step t done

        // ---- combine (MUFU chain) overlapped with xproj(t+1) (tensor pipe) ----
        const float gi = gates_s[cr][cc];
        const float gf = gates_s[cr][64 + cc];
        const float gg = gates_s[cr][128 + cc];
        const float go = gates_s[cr][192 + cc];

        if (t + 1 < Tn) xproj((t + 1) & 1);    // reads x slot (t+1)&1 only

        // prefetch x_{t+2}
        float xn = 0.f;
        if (t + 2 < Tn)
            xn = xin[((size_t)(t + 2) * BnP + b0 + cr) * 64 + cc];

        const float iv = sigm(gi), fv = sigm(gf), gv = htanh(gg), ov = sigm(go);
        cst = fv * cst + iv * gv;
        const float h = ov * htanh(cst);

        // h into B-tile h slot
        {
            float hh = bfr(h);
            in_hi[cr][128 + cc] = __float2bfloat16(hh);
            in_lo[cr][128 + cc] = __float2bfloat16(h - hh);
        }
        // x_{t+2} into slot t&1 (slot (t+1)&1 is being consumed by xproj)
        if (t + 2 < Tn) {
            float hh = bfr(xn);
            const int xb = 64 * (t & 1);
            in_hi[cr][xb + cc] = __float2bfloat16(hh);
            in_lo[cr][xb + cc] = __float2bfloat16(xn - hh);
        }
        if (cr < nrows) {
            if constexpr (!LAST)
                outs[((size_t)t * BnP + b0 + cr) * 64 + cc] = h;
            else if (t == Tn - 1)
                h_s[cr][cc] = h;
        }
    }

    if constexpr (LAST) {
        __syncthreads();
        if (tid < nrows * 4) {
            const int r = tid >> 2, o = tid & 3;
            float s = b_fc[o];
#pragma unroll
            for (int k = 0; k < Hn; k++)
                s += h_s[r][k] * w_fc[o * Hn + k];
            out_fc[(b0 + r) * 4 + o] = s;
        }
    }
}

extern "C" void kernel_launch(void* const* d_in, const int* in_sizes, int n_in,
                              void* d_out, int out_size)
{
    const float* x    = (const float*)d_in[0];
    const float* wih0 = (const float*)d_in[1];
    const float* whh0 = (const float*)d_in[2];
    const float* bih0 = (const float*)d_in[3];
    const float* bhh0 = (const float*)d_in[4];
    const float* wih1 = (const float*)d_in[5];
    const float* whh1 = (const float*)d_in[6];
    const float* bih1 = (const float*)d_in[7];
    const float* bhh1 = (const float*)d_in[8];
    const float* wih2 = (const float*)d_in[9];
    const float* whh2 = (const float*)d_in[10];
    const float* bih2 = (const float*)d_in[11];
    const float* bhh2 = (const float*)d_in[12];
    const float* wfc  = (const float*)d_in[13];
    const float* bfc  = (const float*)d_in[14];
    float* out = (float*)d_out;

    transpose_x_k<<<Bn * 8, 256>>>(x);

    dim3 grid(GRID);
    dim3 block(NT);
    lstm_hmma_k<0><<<grid, block>>>(wih0, whh0, bih0, bhh0, nullptr, nullptr, nullptr);
    lstm_hmma_k<1><<<grid, block>>>(wih1, whh1, bih1, bhh1, nullptr, nullptr, nullptr);
    lstm_hmma_k<2><<<grid, block>>>(wih2, whh2, bih2, bhh2, wfc,     bfc,     out);
}

// round 10
// speedup vs baseline: 1.1437x; 1.1437x over previous
#include <cuda_runtime.h>
#include <cuda_bf16.h>
#include <cstdint>
#include <cstddef>

namespace {
constexpr int Bn   = 1024;
constexpr int BnP  = 1032;   // padded rows (zero tail)
constexpr int Tn   = 512;
constexpr int Hn   = 64;
constexpr int NB   = 7;      // real rows per block -> grid 147 (N=8 with pad row)
constexpr int GRID = 147;
constexpr int NT   = 512;    // 16 warps
}

// Inter-layer activations, [t][b][64], f32, rows >=1024 stay zero.
__device__ float g_seq0[(size_t)Tn * BnP * 64];
__device__ float g_seq1[(size_t)Tn * BnP * 64];
// Layer-0 input transposed+padded: [t][b][64] (cols 22..63 zero)
__device__ float g_x64[(size_t)Tn * BnP * 64];

__device__ __forceinline__ float htanh(float x) {   // HW MUFU.TANH
    float y;
    asm("tanh.approx.f32 %0, %1;" : "=f"(y) : "f"(x));
    return y;
}
__device__ __forceinline__ float sigm(float x) {    // 0.5 + 0.5*tanh(x/2)
    return fmaf(htanh(0.5f * x), 0.5f, 0.5f);
}
__device__ __forceinline__ uint32_t bf2(float a, float b) {
    __nv_bfloat162 t = __floats2bfloat162_rn(a, b);
    return *reinterpret_cast<uint32_t*>(&t);
}
__device__ __forceinline__ float bfr(float v) {
    return __bfloat162float(__float2bfloat16(v));
}

// m16n8k16 bf16 MMA, fp32 accumulate (sm_80 baseline PTX).
__device__ __forceinline__ void hmma(float& d0, float& d1, float& d2, float& d3,
                                     uint32_t a0, uint32_t a1, uint32_t a2, uint32_t a3,
                                     uint32_t b0, uint32_t b1) {
    asm volatile(
        "mma.sync.aligned.m16n8k16.row.col.f32.bf16.bf16.f32 "
        "{%0,%1,%2,%3}, {%4,%5,%6,%7}, {%8,%9}, {%0,%1,%2,%3};"
        : "+f"(d0), "+f"(d1), "+f"(d2), "+f"(d3)
        : "r"(a0), "r"(a1), "r"(a2), "r"(a3), "r"(b0), "r"(b1));
}

// Transpose x[b][22][t] -> g_x64[t][b][0..63] (cols 22..63 zero).
__global__ void __launch_bounds__(256)
transpose_x_k(const float* __restrict__ x)
{
    const int b  = blockIdx.x >> 3;
    const int t0 = (blockIdx.x & 7) * 64;
    __shared__ float tile[22][65];
    for (int e = threadIdx.x; e < 22 * 64; e += 256) {
        int i = e / 64, tt = e - i * 64;
        tile[i][tt] = x[(size_t)b * (22 * Tn) + i * Tn + t0 + tt];
    }
    __syncthreads();
    for (int e = threadIdx.x; e < 64 * 64; e += 256) {
        int tt = e >> 6, i = e & 31 | (e & 32);   // i = e & 63
        i = e & 63;
        g_x64[((size_t)(t0 + tt) * BnP + b) * 64 + i] = (i < 22) ? tile[i][tt] : 0.f;
    }
}

// LSTM layer, HMMA tensor cores, warp-local combine via row permutation.
// Warp w's m16 A-tile rows (via gathered weight loads):
//   r_local gid      (0..7):  gate (gid>>2 ? f : i), cell 4w + (gid&3)
//   r_local gid+8    (8..15): gate (gid>>2 ? o : g), cell 4w + (gid&3)
// After MMA, lane (gid,qid) holds 2 gates x 2 batch rows for ONE cell;
// shfl.bfly(16) brings the other 2 gates -> combine entirely in-warp.
// B tile bf16 hi/lo, row stride 200 (u32 stride 100):
//   cols [0,64) x slot 0, [64,128) x slot 1 (parity), [128,192) h_{t-1}.
// ONE __syncthreads per step.
template<int LAYER>
__global__ void __launch_bounds__(NT, 1)
lstm_hmma_k(const float* __restrict__ w_ih, const float* __restrict__ w_hh,
            const float* __restrict__ b_ih, const float* __restrict__ b_hh,
            const float* __restrict__ w_fc, const float* __restrict__ b_fc,
            float* __restrict__ out_fc)
{
    constexpr bool LAST = (LAYER == 2);
    constexpr int  DIN  = (LAYER == 0) ? 22 : 64;
    constexpr int  XCH  = (LAYER == 0) ? 2 : 4;     // x k-chunks (cols >=32 zero for L0)
    const float* xin  = (LAYER == 0) ? g_x64 : (LAYER == 1 ? g_seq0 : g_seq1);
    float*       outs = (LAYER == 0) ? g_seq0 : (LAYER == 1 ? g_seq1 : nullptr);

    __shared__ __align__(16) __nv_bfloat16 in_hi[8][200];
    __shared__ __align__(16) __nv_bfloat16 in_lo[8][200];
    __shared__ float h_out[2][8][68];    // f32 h, parity-buffered, padded stride

    const int tid  = threadIdx.x;
    const int lane = tid & 31;
    const int wrp  = tid >> 5;
    const int gid  = lane >> 2;          // 0..7
    const int qid  = lane & 3;           // 0..3
    const int b0   = blockIdx.x * NB;
    const int nrows = (Bn - b0 < NB) ? (Bn - b0) : NB;

    // permuted weight rows for this lane's fragments
    const int cell = 4 * wrp + (gid & 3);
    const int m0 = ((gid >> 2) ? 64 : 0)   + cell;   // i or f row
    const int m1 = ((gid >> 2) ? 192 : 128) + cell;  // g or o row

    // ---- weight fragments (hi + lo bf16 split), registers ----
    uint32_t axh[XCH][4], axl[XCH][4];   // x cols [0,64)
    uint32_t ahh[4][4],   ahl[4][4];     // h cols [64,128) of concat
    {
        auto pair = [&](float p0, float p1, uint32_t& hi, uint32_t& lo) {
            float h0 = bfr(p0), h1 = bfr(p1);
            hi = bf2(h0, h1);
            lo = bf2(p0 - h0, p1 - h1);
        };
        auto wx = [&](int m, int k) -> float {
            return (k < DIN) ? w_ih[m * DIN + k] : 0.f;
        };
#pragma unroll
        for (int kc = 0; kc < XCH; kc++) {
            const int k0 = kc * 16 + qid * 2, k1 = k0 + 8;
            pair(wx(m0, k0), wx(m0, k0 + 1), axh[kc][0], axl[kc][0]);
            pair(wx(m1, k0), wx(m1, k0 + 1), axh[kc][1], axl[kc][1]);
            pair(wx(m0, k1), wx(m0, k1 + 1), axh[kc][2], axl[kc][2]);
            pair(wx(m1, k1), wx(m1, k1 + 1), axh[kc][3], axl[kc][3]);
        }
#pragma unroll
        for (int kc = 0; kc < 4; kc++) {
            const int k0 = kc * 16 + qid * 2, k1 = k0 + 8;
            pair(w_hh[m0 * 64 + k0], w_hh[m0 * 64 + k0 + 1], ahh[kc][0], ahl[kc][0]);
            pair(w_hh[m1 * 64 + k0], w_hh[m1 * 64 + k0 + 1], ahh[kc][1], ahl[kc][1]);
            pair(w_hh[m0 * 64 + k1], w_hh[m0 * 64 + k1 + 1], ahh[kc][2], ahl[kc][2]);
            pair(w_hh[m1 * 64 + k1], w_hh[m1 * 64 + k1 + 1], ahh[kc][3], ahl[kc][3]);
        }
    }
    const float biasA = b_ih[m0] + b_hh[m0];
    const float biasB = b_ih[m1] + b_hh[m1];

    // combine identities
    const bool sideA = (lane < 16);       // holds i,g; writes h into B tile
    const int  r0 = 2 * qid, r1 = 2 * qid + 1;
    float cst0 = 0.f, cst1 = 0.f;

    // staging identity (coalesced x load / outs store)
    const int sr = tid >> 6;              // 0..7
    const int sc = tid & 63;

    // ---- zero B tiles ----
    for (int e = tid; e < 8 * 200; e += NT) {
        (&in_hi[0][0])[e] = __float2bfloat16(0.f);
        (&in_lo[0][0])[e] = __float2bfloat16(0.f);
    }
    __syncthreads();
    // stage x_0 -> slot 0, x_1 -> slot 1
    {
        float v0 = xin[((size_t)0 * BnP + b0 + sr) * 64 + sc];
        float h0 = bfr(v0);
        in_hi[sr][sc] = __float2bfloat16(h0);
        in_lo[sr][sc] = __float2bfloat16(v0 - h0);
        float v1 = (Tn > 1) ? xin[((size_t)1 * BnP + b0 + sr) * 64 + sc] : 0.f;
        float h1 = bfr(v1);
        in_hi[sr][64 + sc] = __float2bfloat16(h1);
        in_lo[sr][64 + sc] = __float2bfloat16(v1 - h1);
    }
    __syncthreads();

    const uint32_t* rowH = reinterpret_cast<const uint32_t*>(&in_hi[gid][0]) + qid;
    const uint32_t* rowL = reinterpret_cast<const uint32_t*>(&in_lo[gid][0]) + qid;

    // xproj(slot): W_x · x + bias -> carried cx registers (3-term bf16 split).
    float cx0, cx1, cx2, cx3;
    auto xproj = [&](int slot) {
        float d0 = biasA, d1 = biasA, d2 = biasB, d3 = biasB;
        float e0 = 0.f, e1 = 0.f, e2 = 0.f, e3 = 0.f;
        float f0 = 0.f, f1 = 0.f, f2 = 0.f, f3 = 0.f;
        const int wb = 32 * slot;
#pragma unroll
        for (int kc = 0; kc < XCH; kc++) {
            const uint32_t bh0 = rowH[wb + kc * 8];
            const uint32_t bh1 = rowH[wb + kc * 8 + 4];
            const uint32_t bl0 = rowL[wb + kc * 8];
            const uint32_t bl1 = rowL[wb + kc * 8 + 4];
            hmma(d0, d1, d2, d3, axh[kc][0], axh[kc][1], axh[kc][2], axh[kc][3], bh0, bh1);
            hmma(e0, e1, e2, e3, axh[kc][0], axh[kc][1], axh[kc][2], axh[kc][3], bl0, bl1);
            hmma(f0, f1, f2, f3, axl[kc][0], axl[kc][1], axl[kc][2], axl[kc][3], bh0, bh1);
        }
        cx0 = d0 + e0 + f0; cx1 = d1 + e1 + f1;
        cx2 = d2 + e2 + f2; cx3 = d3 + e3 + f3;
    };

    xproj(0);   // carried for t=0

    for (int t = 0; t < Tn; t++) {
        __syncthreads();   // ONE barrier: h(t-1) + x slots staged; h_out(t-1) ready

        // ---- coalesced flush of h(t-1) to global (off critical path) ----
        if (t > 0 && sr < nrows) {
            if constexpr (!LAST)
                outs[((size_t)(t - 1) * BnP + b0 + sr) * 64 + sc] = h_out[(t - 1) & 1][sr][sc];
        }

        // ---- critical path: W_h · h_{t-1}, init = carried xproj(t) ----
        float d0 = cx0, d1 = cx1, d2 = cx2, d3 = cx3;
        float e0 = 0.f, e1 = 0.f, e2 = 0.f, e3 = 0.f;
        float f0 = 0.f, f1 = 0.f, f2 = 0.f, f3 = 0.f;
#pragma unroll
        for (int kc = 0; kc < 4; kc++) {
            const uint32_t bh0 = rowH[64 + kc * 8];
            const uint32_t bh1 = rowH[64 + kc * 8 + 4];
            const uint32_t bl0 = rowL[64 + kc * 8];
            const uint32_t bl1 = rowL[64 + kc * 8 + 4];
            hmma(d0, d1, d2, d3, ahh[kc][0], ahh[kc][1], ahh[kc][2], ahh[kc][3], bh0, bh1);
            hmma(e0, e1, e2, e3, ahh[kc][0], ahh[kc][1], ahh[kc][2], ahh[kc][3], bl0, bl1);
            hmma(f0, f1, f2, f3, ahl[kc][0], ahl[kc][1], ahl[kc][2], ahl[kc][3], bh0, bh1);
        }
        d0 += e0 + f0; d1 += e1 + f1; d2 += e2 + f2; d3 += e3 + f3;

        // ---- off-path: xproj(t+1) (independent accumulators, fills tensor pipe)
        if (t + 1 < Tn) xproj((t + 1) & 1);

        // prefetch x_{t+2}
        float xn = 0.f;
        if (t + 2 < Tn)
            xn = xin[((size_t)(t + 2) * BnP + b0 + sr) * 64 + sc];

        // ---- warp-local gate gather: bfly(16) swaps (i,g)<->(f,o) ----
        const float p0 = __shfl_xor_sync(0xffffffffu, d0, 16);
        const float p1 = __shfl_xor_sync(0xffffffffu, d1, 16);
        const float p2 = __shfl_xor_sync(0xffffffffu, d2, 16);
        const float p3 = __shfl_xor_sync(0xffffffffu, d3, 16);

        const float gi0 = sideA ? d0 : p0, gf0 = sideA ? p0 : d0;
        const float gg0 = sideA ? d2 : p2, go0 = sideA ? p2 : d2;
        const float gi1 = sideA ? d1 : p1, gf1 = sideA ? p1 : d1;
        const float gg1 = sideA ? d3 : p3, go1 = sideA ? p3 : d3;

        // ---- combine (both sides compute; each lane: 1 cell x 2 rows) ----
        const float iv0 = sigm(gi0), fv0 = sigm(gf0), gv0 = htanh(gg0), ov0 = sigm(go0);
        const float iv1 = sigm(gi1), fv1 = sigm(gf1), gv1 = htanh(gg1), ov1 = sigm(go1);
        cst0 = fv0 * cst0 + iv0 * gv0;
        cst1 = fv1 * cst1 + iv1 * gv1;
        const float h0 = ov0 * htanh(cst0);
        const float h1 = ov1 * htanh(cst1);

        if (sideA) {   // h into B tile (bf16 hi/lo) for next step's GEMM
            float hh0 = bfr(h0), hh1 = bfr(h1);
            in_hi[r0][128 + cell] = __float2bfloat16(hh0);
            in_lo[r0][128 + cell] = __float2bfloat16(h0 - hh0);
            in_hi[r1][128 + cell] = __float2bfloat16(hh1);
            in_lo[r1][128 + cell] = __float2bfloat16(h1 - hh1);
        } else {       // f32 h into parity staging buffer
            h_out[t & 1][r0][cell] = h0;
            h_out[t & 1][r1][cell] = h1;
        }

        // x_{t+2} into slot t&1 (slot (t+1)&1 is being consumed by xproj)
        if (t + 2 < Tn) {
            float hh = bfr(xn);
            const int xb = 64 * (t & 1);
            in_hi[sr][xb + sc] = __float2bfloat16(hh);
            in_lo[sr][xb + sc] = __float2bfloat16(xn - hh);
        }
    }

    __syncthreads();
    if constexpr (!LAST) {
        if (sr < nrows)
            outs[((size_t)(Tn - 1) * BnP + b0 + sr) * 64 + sc] = h_out[(Tn - 1) & 1][sr][sc];
    } else {
        if (tid < nrows * 4) {
            const int r = tid >> 2, o = tid & 3;
            float s = b_fc[o];
#pragma unroll
            for (int k = 0; k < Hn; k++)
                s += h_out[(Tn - 1) & 1][r][k] * w_fc[o * Hn + k];
            out_fc[(b0 + r) * 4 + o] = s;
        }
    }
}

extern "C" void kernel_launch(void* const* d_in, const int* in_sizes, int n_in,
                              void* d_out, int out_size)
{
    const float* x    = (const float*)d_in[0];
    const float* wih0 = (const float*)d_in[1];
    const float* whh0 = (const float*)d_in[2];
    const float* bih0 = (const float*)d_in[3];
    const float* bhh0 = (const float*)d_in[4];
    const float* wih1 = (const float*)d_in[5];
    const float* whh1 = (const float*)d_in[6];
    const float* bih1 = (const float*)d_in[7];
    const float* bhh1 = (const float*)d_in[8];
    const float* wih2 = (const float*)d_in[9];
    const float* whh2 = (const float*)d_in[10];
    const float* bih2 = (const float*)d_in[11];
    const float* bhh2 = (const float*)d_in[12];
    const float* wfc  = (const float*)d_in[13];
    const float* bfc  = (const float*)d_in[14];
    float* out = (float*)d_out;

    transpose_x_k<<<Bn * 8, 256>>>(x);

    dim3 grid(GRID);
    dim3 block(NT);
    lstm_hmma_k<0><<<grid, block>>>(wih0, whh0, bih0, bhh0, nullptr, nullptr, nullptr);
    lstm_hmma_k<1><<<grid, block>>>(wih1, whh1, bih1, bhh1, nullptr, nullptr, nullptr);
    lstm_hmma_k<2><<<grid, block>>>(wih2, whh2, bih2, bhh2, wfc,     bfc,     out);
}